// round 14
// baseline (speedup 1.0000x reference)
#include <cuda_runtime.h>
#include <cstdint>
#include <math.h>

// Problem constants (fixed: VOCAB=32, EMB=64, HID=1024, BATCH=2048, MAXLEN=100)
#define BATCH  2048
#define HID    1024
#define EMB    64
#define VOCAB  32
#define MAXLEN 100
#define SEQW   (MAXLEN+1)
#define PADTOK 0
#define EOSTOK 2

#define NCTA   512      // CTAs; each owns RPC rows for the whole generation
#define RPC    4        // rows per CTA
#define TPB    512      // threads per CTA; each owns 2 hidden cols (t, t+512)

// Evidence log:
//  R1-8:  large __device__ data segments tripped the 128MiB mem guard ->
//         no device globals; all state in static SMEM of a persistent kernel.
//  R10-13: kernel runs cleanly yet rel_err EXACTLY 1.000000e+00, invariant to
//         config and RNG scheme. Only consistent model: __output__ dtype is
//         float32; our int32 writes reinterpret as denormals ~1e-45 -> the
//         comparator sees all-zeros -> ||a-b||/||b|| == 1.0 exactly.
//  THIS ROUND: write output as float32 (tokens/lengths are small ints, exactly
//         representable). Everything else unchanged from R13.

struct __align__(16) Smem {
    float h0[HID][RPC];        // 16KB  layer-0 h, [k][row], updated in place
    float h1[HID][RPC];        // 16KB  layer-1 h
    float xs[EMB][RPC];        // 1KB   emb[prev] gather, [k][row]
    float part[RPC][VOCAB];    // 512B  logit partials
    uint2 keys[MAXLEN];        // 800B  per-step jax keys
    int   prev[RPC];
    int   isend[RPC];
    int   len[RPC];
};                             // ~34.8KB static shared (<48KB, no opt-in)

// ---------------- Threefry-2x32 (matches jax._src.prng) ----------------
__device__ __forceinline__ uint2 tf2x32(uint2 k, uint2 x) {
    uint32_t ks0 = k.x, ks1 = k.y, ks2 = k.x ^ k.y ^ 0x1BD11BDAu;
    uint32_t x0 = x.x + ks0, x1 = x.y + ks1;
#define TFR(r) { x0 += x1; x1 = __funnelshift_l(x1, x1, (r)); x1 ^= x0; }
    TFR(13) TFR(15) TFR(26) TFR(6)   x0 += ks1; x1 += ks2 + 1u;
    TFR(17) TFR(29) TFR(16) TFR(24)  x0 += ks2; x1 += ks0 + 2u;
    TFR(13) TFR(15) TFR(26) TFR(6)   x0 += ks0; x1 += ks1 + 3u;
    TFR(17) TFR(29) TFR(16) TFR(24)  x0 += ks1; x1 += ks2 + 4u;
    TFR(13) TFR(15) TFR(26) TFR(6)   x0 += ks2; x1 += ks0 + 5u;
#undef TFR
    return make_uint2(x0, x1);
}

// XLA expands logistic(x) as 0.5 + 0.5*tanh(0.5*x)
__device__ __forceinline__ float sigmoid_x(float x) { return 0.5f * tanhf(0.5f * x) + 0.5f; }

// acc[g][r] += sum_k As[k][r] * W[g*HID+col][k]   (K = inner length)
__device__ __forceinline__ void kpass4(float (&acc)[4][RPC],
                                       const float* __restrict__ W,
                                       const float* As, int col, int K) {
    const float* wp0 = W + (size_t)(0 * HID + col) * K;
    const float* wp1 = W + (size_t)(1 * HID + col) * K;
    const float* wp2 = W + (size_t)(2 * HID + col) * K;
    const float* wp3 = W + (size_t)(3 * HID + col) * K;
    for (int k0 = 0; k0 < K; k0 += 4) {
        float4 w0 = __ldg((const float4*)(wp0 + k0));
        float4 w1 = __ldg((const float4*)(wp1 + k0));
        float4 w2 = __ldg((const float4*)(wp2 + k0));
        float4 w3 = __ldg((const float4*)(wp3 + k0));
        float wa[4][4] = {{w0.x, w0.y, w0.z, w0.w},
                          {w1.x, w1.y, w1.z, w1.w},
                          {w2.x, w2.y, w2.z, w2.w},
                          {w3.x, w3.y, w3.z, w3.w}};
        #pragma unroll
        for (int kk = 0; kk < 4; kk++) {
            float4 av = *(const float4*)(As + (size_t)(k0 + kk) * RPC);
            float ar[4] = {av.x, av.y, av.z, av.w};
            #pragma unroll
            for (int g = 0; g < 4; g++)
                #pragma unroll
                for (int r = 0; r < RPC; r++)
                    acc[g][r] = fmaf(wa[g][kk], ar[r], acc[g][r]);
        }
    }
}

__global__ __launch_bounds__(TPB, 1)
void organ_persistent(const int* __restrict__ prevs, const float* __restrict__ emb,
                      const float* __restrict__ Wih0, const float* __restrict__ Whh0,
                      const float* __restrict__ bih0, const float* __restrict__ bhh0,
                      const float* __restrict__ Wih1, const float* __restrict__ Whh1,
                      const float* __restrict__ bih1, const float* __restrict__ bhh1,
                      const float* __restrict__ Wout, const float* __restrict__ bout,
                      float* __restrict__ out, int write_len) {
    __shared__ Smem S;
    const int t = threadIdx.x;
    const int rowBase = blockIdx.x * RPC;

    // registers: cell state for this thread's two columns (t, t+512)
    float c0r[2][RPC], c1r[2][RPC];
    #pragma unroll
    for (int ch = 0; ch < 2; ch++)
        #pragma unroll
        for (int r = 0; r < RPC; r++) { c0r[ch][r] = 0.f; c1r[ch][r] = 0.f; }

    // ---- init shared state ----
    for (int i = t; i < HID * RPC; i += TPB) {
        (&S.h0[0][0])[i] = 0.f;
        (&S.h1[0][0])[i] = 0.f;
    }
    if (t < RPC) {
        int p = prevs[rowBase + t];
        S.prev[t]  = p & (VOCAB - 1);          // clamped: crash-proof gather
        S.isend[t] = (p == EOSTOK) ? 1 : 0;
        S.len[t]   = 0;
        out[(size_t)(rowBase + t) * SEQW] = (float)p;   // FLOAT output
    }
    if (t < MAXLEN) {
        // jax.random.split, threefry_partitionable=True (JAX >= 0.4.30 default,
        // typed-key API): _threefry_split_foldlike ->
        // keys[i] = threefry2x32(key, (hi=0, lo=i)) -> (out0, out1)
        S.keys[t] = tf2x32(make_uint2(0u, 42u), make_uint2(0u, (uint32_t)t));
    }
    __syncthreads();

    for (int s = 0; s < MAXLEN; s++) {
        // ---- gather x = emb[prev] into xs[k][r] ----
        if (t < EMB * RPC) {
            int k = t >> 2, r = t & (RPC - 1);
            S.xs[k][r] = emb[(S.prev[r] & (VOCAB - 1)) * EMB + k];
        }
        __syncthreads();

        // ---- layer 0: gates = h0 @ Whh0^T + x @ Wih0^T + bih0 + bhh0 ----
        float hb[2][RPC];
        {
            #pragma unroll 1
            for (int ch = 0; ch < 2; ch++) {
                int col = ch * TPB + t;
                float acc[4][RPC];
                #pragma unroll
                for (int g = 0; g < 4; g++)
                    #pragma unroll
                    for (int r = 0; r < RPC; r++) acc[g][r] = 0.f;
                kpass4(acc, Whh0, &S.h0[0][0], col, HID);
                kpass4(acc, Wih0, &S.xs[0][0], col, EMB);
                float bv0 = bih0[0*HID + col] + bhh0[0*HID + col];
                float bv1 = bih0[1*HID + col] + bhh0[1*HID + col];
                float bv2 = bih0[2*HID + col] + bhh0[2*HID + col];
                float bv3 = bih0[3*HID + col] + bhh0[3*HID + col];
                #pragma unroll
                for (int r = 0; r < RPC; r++) {
                    float gi = acc[0][r] + bv0, gf = acc[1][r] + bv1;
                    float gg = acc[2][r] + bv2, go = acc[3][r] + bv3;
                    float cn = sigmoid_x(gf) * c0r[ch][r] + sigmoid_x(gi) * tanhf(gg);
                    c0r[ch][r] = cn;
                    hb[ch][r] = sigmoid_x(go) * tanhf(cn);
                }
            }
        }
        __syncthreads();   // all reads of old h0 complete
        #pragma unroll
        for (int ch = 0; ch < 2; ch++) {
            int col = ch * TPB + t;
            #pragma unroll
            for (int r = 0; r < RPC; r++) S.h0[col][r] = hb[ch][r];
        }
        __syncthreads();   // new h0 visible

        // ---- layer 1: gates = h0_new @ Wih1^T + h1 @ Whh1^T + bih1 + bhh1 ----
        {
            #pragma unroll 1
            for (int ch = 0; ch < 2; ch++) {
                int col = ch * TPB + t;
                float acc[4][RPC];
                #pragma unroll
                for (int g = 0; g < 4; g++)
                    #pragma unroll
                    for (int r = 0; r < RPC; r++) acc[g][r] = 0.f;
                kpass4(acc, Wih1, &S.h0[0][0], col, HID);
                kpass4(acc, Whh1, &S.h1[0][0], col, HID);
                float bv0 = bih1[0*HID + col] + bhh1[0*HID + col];
                float bv1 = bih1[1*HID + col] + bhh1[1*HID + col];
                float bv2 = bih1[2*HID + col] + bhh1[2*HID + col];
                float bv3 = bih1[3*HID + col] + bhh1[3*HID + col];
                #pragma unroll
                for (int r = 0; r < RPC; r++) {
                    float gi = acc[0][r] + bv0, gf = acc[1][r] + bv1;
                    float gg = acc[2][r] + bv2, go = acc[3][r] + bv3;
                    float cn = sigmoid_x(gf) * c1r[ch][r] + sigmoid_x(gi) * tanhf(gg);
                    c1r[ch][r] = cn;
                    hb[ch][r] = sigmoid_x(go) * tanhf(cn);
                }
            }
        }
        __syncthreads();   // all reads of old h1 complete
        #pragma unroll
        for (int ch = 0; ch < 2; ch++) {
            int col = ch * TPB + t;
            #pragma unroll
            for (int r = 0; r < RPC; r++) S.h1[col][r] = hb[ch][r];
        }
        __syncthreads();   // new h1 visible

        // ---- logits: part[r][v] = sum_k h1[k][r] * Wout[v][k] ----
        {
            int v = t >> 4;            // 0..31
            int kb = t & 15;           // k-lane within group of 16
            const float* wv = Wout + (size_t)v * HID;
            float p[RPC];
            #pragma unroll
            for (int r = 0; r < RPC; r++) p[r] = 0.f;
            for (int k = kb; k < HID; k += 16) {
                float w = __ldg(wv + k);
                const float* hk = &S.h1[k][0];
                #pragma unroll
                for (int r = 0; r < RPC; r++) p[r] = fmaf(hk[r], w, p[r]);
            }
            #pragma unroll
            for (int off = 8; off >= 1; off >>= 1)
                #pragma unroll
                for (int r = 0; r < RPC; r++)
                    p[r] += __shfl_down_sync(0xffffffffu, p[r], off, 16);
            if (kb == 0)
                #pragma unroll
                for (int r = 0; r < RPC; r++) S.part[r][v] = p[r];
        }
        __syncthreads();

        // ---- jax.random.categorical + state update (warp r -> row r) ----
        if (t < RPC * 32) {
            int r = t >> 5, v = t & 31;
            int gr = rowBase + r;
            float logit = S.part[r][v] + bout[v];

            // random_bits, partitionable foldlike: element idx of shape
            // (2048,32) -> counts (hi=0, lo=idx); bits = out0 ^ out1.
            uint2 key = S.keys[s];
            uint32_t idx = (uint32_t)(gr * VOCAB + v);
            uint2 o = tf2x32(key, make_uint2(0u, idx));
            uint32_t bits = o.x ^ o.y;

            // jax.random.uniform(minval=tiny, maxval=1.0) for f32
            const float tiny = 1.17549435e-38f;
            float f = __uint_as_float((bits >> 9) | 0x3f800000u) - 1.0f;
            float u = fmaxf(f * (1.0f - tiny) + tiny, tiny);
            float gmb = -logf(-logf(u));
            float val = gmb + logit;

            int bi = v;   // first-index argmax (jnp.argmax semantics)
            #pragma unroll
            for (int off = 16; off > 0; off >>= 1) {
                float ov = __shfl_down_sync(0xffffffffu, val, off);
                int   oi = __shfl_down_sync(0xffffffffu, bi, off);
                if (ov > val || (ov == val && oi < bi)) { val = ov; bi = oi; }
            }
            if (v == 0) {
                int old_end = S.isend[r];
                int tok = old_end ? PADTOK : bi;
                if (!old_end) S.len[r] += 1;
                S.isend[r] = old_end | (tok == EOSTOK);
                S.prev[r] = tok;                 // always in [0,32)
                out[(size_t)gr * SEQW + s + 1] = (float)tok;   // FLOAT output
            }
        }
        __syncthreads();
    }

    if (write_len && t < RPC)
        out[(size_t)BATCH * SEQW + rowBase + t] = (float)(S.len[t] + 1);  // FLOAT
}

// ---------------- launcher: resolve input roles by size signature -----------
extern "C" void kernel_launch(void* const* d_in, const int* in_sizes, int n_in,
                              void* d_out, int out_size) {
    // Expected element counts: prevs 2048, emb 2048, Wih0 262144,
    // Whh0/Wih1/Whh1 4194304, biases 4096, Wout 32768, bout 32, max_len 1.
    int iprevs, iemb, iWih0, iWhh0, ibih0, ibhh0, iWih1, iWhh1, ibih1, ibhh1, iWout, ibout;
    if (n_in >= 12 && in_sizes[0] == 2048 && in_sizes[1] == 2048) {
        // setup_inputs() dict order
        iprevs=0; iemb=1; iWih0=2; iWhh0=3; ibih0=4; ibhh0=5;
        iWih1=6; iWhh1=7; ibih1=8; ibhh1=9; iWout=10; ibout=11;
    } else if (n_in >= 13 && in_sizes[0] == 4194304) {
        // case-sensitive alphabetical: Whh0,Whh1,Wih0,Wih1,Wout,bhh0,bhh1,
        //                              bih0,bih1,bout,emb,max_len,prevs
        iWhh0=0; iWhh1=1; iWih0=2; iWih1=3; iWout=4; ibhh0=5; ibhh1=6;
        ibih0=7; ibih1=8; ibout=9; iemb=10; iprevs=12;
        if (in_sizes[11] == 2048 && in_sizes[12] != 2048) iprevs = 11;
    } else if (n_in >= 13 && in_sizes[0] == 4096) {
        // case-insensitive alphabetical: bhh0,bhh1,bih0,bih1,bout,emb,max_len,
        //                                prevs,Whh0,Whh1,Wih0,Wih1,Wout
        ibhh0=0; ibhh1=1; ibih0=2; ibih1=3; ibout=4; iemb=5; iprevs=7;
        iWhh0=8; iWhh1=9; iWih0=10; iWih1=11; iWout=12;
        if (in_sizes[6] == 2048 && in_sizes[7] != 2048) {
            iprevs=6; iWhh0=7; iWhh1=8; iWih0=9; iWih1=10; iWout=11;
        }
    } else {
        iprevs=0; iemb=1; iWih0=2; iWhh0=3; ibih0=4; ibhh0=5;
        iWih1=6; iWhh1=7; ibih1=8; ibhh1=9; iWout=10; ibout=11;
    }

    const int*   prevs = (const int*)d_in[iprevs];
    const float* emb   = (const float*)d_in[iemb];
    const float* Wih0  = (const float*)d_in[iWih0];
    const float* Whh0  = (const float*)d_in[iWhh0];
    const float* bih0  = (const float*)d_in[ibih0];
    const float* bhh0  = (const float*)d_in[ibhh0];
    const float* Wih1  = (const float*)d_in[iWih1];
    const float* Whh1  = (const float*)d_in[iWhh1];
    const float* bih1  = (const float*)d_in[ibih1];
    const float* bhh1  = (const float*)d_in[ibhh1];
    const float* Wout  = (const float*)d_in[iWout];
    const float* bout  = (const float*)d_in[ibout];
    float* out = (float*)d_out;   // __output__ dtype: float32 (R10-13 evidence)

    int write_len = (out_size >= BATCH * SEQW + BATCH) ? 1 : 0;
    organ_persistent<<<NCTA, TPB>>>(
        prevs, emb, Wih0, Whh0, bih0, bhh0, Wih1, Whh1, bih1, bhh1,
        Wout, bout, out, write_len);
}

// round 15
// speedup vs baseline: 4.1370x; 4.1370x over previous
#include <cuda_runtime.h>
#include <cstdint>
#include <math.h>

// Problem constants (fixed: VOCAB=32, EMB=64, HID=1024, BATCH=2048, MAXLEN=100)
#define BATCH  2048
#define HID    1024
#define EMB    64
#define VOCAB  32
#define MAXLEN 100
#define SEQW   (MAXLEN+1)
#define PADTOK 0
#define EOSTOK 2

#define NCTA   256     // CTAs; each owns RPC rows for the whole generation
#define RPC    8       // rows per CTA
#define TPB    512     // threads; warp = 4 cols x 8 k-lanes
#define NPASS  16      // column passes: 16 * 64 cols = 1024
#define HS     1028    // padded k-stride for h/c tiles (bank-conflict-free)
#define XS     68      // padded k-stride for x tile

// R14 ncu: L1tex 86% (bottleneck), fma 10.5%, DRAM 0%. Cause: per-thread
// weight rows -> 32 L1 wavefronts per warp LDG. This round: k-sliced warps
// (4 cols x 8 k-lanes) -> coalesced 128B weight lines (4 wavefronts), RPC=8
// halves L2 traffic, butterfly-reduce + per-lane cell update.

struct Smem {
    float h0[2][RPC][HS];     // 65.8KB  layer-0 h, [buf][row][k]
    float h1[2][RPC][HS];     // 65.8KB
    float c0[RPC][HS];        // 32.9KB
    float c1[RPC][HS];        // 32.9KB
    float xs[RPC][XS];        // 2.2KB   emb[prev] gather, [row][k]
    float part[RPC][VOCAB];   // 1KB
    uint2 keys[MAXLEN];       // 800B
    int   prev[RPC];
    int   isend[RPC];
    int   len[RPC];
};                            // ~201.5KB dynamic shared

// ---------------- Threefry-2x32 (matches jax._src.prng) ----------------
__device__ __forceinline__ uint2 tf2x32(uint2 k, uint2 x) {
    uint32_t ks0 = k.x, ks1 = k.y, ks2 = k.x ^ k.y ^ 0x1BD11BDAu;
    uint32_t x0 = x.x + ks0, x1 = x.y + ks1;
#define TFR(r) { x0 += x1; x1 = __funnelshift_l(x1, x1, (r)); x1 ^= x0; }
    TFR(13) TFR(15) TFR(26) TFR(6)   x0 += ks1; x1 += ks2 + 1u;
    TFR(17) TFR(29) TFR(16) TFR(24)  x0 += ks2; x1 += ks0 + 2u;
    TFR(13) TFR(15) TFR(26) TFR(6)   x0 += ks0; x1 += ks1 + 3u;
    TFR(17) TFR(29) TFR(16) TFR(24)  x0 += ks1; x1 += ks2 + 4u;
    TFR(13) TFR(15) TFR(26) TFR(6)   x0 += ks2; x1 += ks0 + 5u;
#undef TFR
    return make_uint2(x0, x1);
}

// XLA expands logistic(x) as 0.5 + 0.5*tanh(0.5*x)
__device__ __forceinline__ float sigmoid_x(float x) { return 0.5f * tanhf(0.5f * x) + 0.5f; }

// Partial GEMM over this lane's k-slice (k = i*32 + kl*4 + kk):
// acc[g][r] += sum_k AsT[r][k] * W[g*HID+col][k].  W loads: 8 kl-lanes cover
// one contiguous 128B line per (g,col) -> coalesced. As loads: float4 per row,
// lanes span a 128B window of the padded row -> conflict-free LDS.128.
__device__ __forceinline__ void kslice(float (&acc)[4][RPC],
                                       const float* __restrict__ W,
                                       const float* __restrict__ AsT, int stride,
                                       int col, int K, int kl) {
    const float* wp0 = W + (size_t)(0 * HID + col) * K + kl * 4;
    const float* wp1 = W + (size_t)(1 * HID + col) * K + kl * 4;
    const float* wp2 = W + (size_t)(2 * HID + col) * K + kl * 4;
    const float* wp3 = W + (size_t)(3 * HID + col) * K + kl * 4;
    const int ni = K >> 5;
    for (int i = 0; i < ni; i++) {
        int koff = i << 5;
        float4 w0 = __ldg((const float4*)(wp0 + koff));
        float4 w1 = __ldg((const float4*)(wp1 + koff));
        float4 w2 = __ldg((const float4*)(wp2 + koff));
        float4 w3 = __ldg((const float4*)(wp3 + koff));
        int kbase = koff + (kl << 2);
        float4 a[RPC];
        #pragma unroll
        for (int r = 0; r < RPC; r++)
            a[r] = *(const float4*)(AsT + r * stride + kbase);
        #pragma unroll
        for (int r = 0; r < RPC; r++) {
            acc[0][r] = fmaf(w0.x, a[r].x, acc[0][r]);
            acc[0][r] = fmaf(w0.y, a[r].y, acc[0][r]);
            acc[0][r] = fmaf(w0.z, a[r].z, acc[0][r]);
            acc[0][r] = fmaf(w0.w, a[r].w, acc[0][r]);
            acc[1][r] = fmaf(w1.x, a[r].x, acc[1][r]);
            acc[1][r] = fmaf(w1.y, a[r].y, acc[1][r]);
            acc[1][r] = fmaf(w1.z, a[r].z, acc[1][r]);
            acc[1][r] = fmaf(w1.w, a[r].w, acc[1][r]);
            acc[2][r] = fmaf(w2.x, a[r].x, acc[2][r]);
            acc[2][r] = fmaf(w2.y, a[r].y, acc[2][r]);
            acc[2][r] = fmaf(w2.z, a[r].z, acc[2][r]);
            acc[2][r] = fmaf(w2.w, a[r].w, acc[2][r]);
            acc[3][r] = fmaf(w3.x, a[r].x, acc[3][r]);
            acc[3][r] = fmaf(w3.y, a[r].y, acc[3][r]);
            acc[3][r] = fmaf(w3.z, a[r].z, acc[3][r]);
            acc[3][r] = fmaf(w3.w, a[r].w, acc[3][r]);
        }
    }
}

// Reduce over the 8 k-lanes, add biases, apply LSTM cell for row kl, store h,c.
__device__ __forceinline__ void reduce_cell(float (&acc)[4][RPC],
                                            const float* __restrict__ bih,
                                            const float* __restrict__ bhh,
                                            float* __restrict__ crow,   // &c[0][0]
                                            float* __restrict__ hrow,   // &h_new[0][0]
                                            int col, int kl) {
    #pragma unroll
    for (int g = 0; g < 4; g++)
        #pragma unroll
        for (int r = 0; r < RPC; r++) {
            acc[g][r] += __shfl_xor_sync(0xffffffffu, acc[g][r], 1);
            acc[g][r] += __shfl_xor_sync(0xffffffffu, acc[g][r], 2);
            acc[g][r] += __shfl_xor_sync(0xffffffffu, acc[g][r], 4);
        }
    float gi = 0.f, gf = 0.f, gg = 0.f, go = 0.f;
    #pragma unroll
    for (int r = 0; r < RPC; r++)
        if (kl == r) { gi = acc[0][r]; gf = acc[1][r]; gg = acc[2][r]; go = acc[3][r]; }
    gi += bih[col]         + bhh[col];
    gf += bih[HID + col]   + bhh[HID + col];
    gg += bih[2*HID + col] + bhh[2*HID + col];
    go += bih[3*HID + col] + bhh[3*HID + col];
    float cold = crow[kl * HS + col];
    float cn = sigmoid_x(gf) * cold + sigmoid_x(gi) * tanhf(gg);
    crow[kl * HS + col] = cn;
    hrow[kl * HS + col] = sigmoid_x(go) * tanhf(cn);
}

__global__ __launch_bounds__(TPB, 1)
void organ_persistent(const int* __restrict__ prevs, const float* __restrict__ emb,
                      const float* __restrict__ Wih0, const float* __restrict__ Whh0,
                      const float* __restrict__ bih0, const float* __restrict__ bhh0,
                      const float* __restrict__ Wih1, const float* __restrict__ Whh1,
                      const float* __restrict__ bih1, const float* __restrict__ bhh1,
                      const float* __restrict__ Wout, const float* __restrict__ bout,
                      float* __restrict__ out, int write_len) {
    extern __shared__ char smem_raw[];
    Smem& S = *reinterpret_cast<Smem*>(smem_raw);
    const int t = threadIdx.x;
    const int w = t >> 5;
    const int c = (t >> 3) & 3;
    const int kl = t & 7;
    const int rowBase = blockIdx.x * RPC;

    // ---- init shared state ----
    for (int i = t; i < RPC * HS; i += TPB) {
        (&S.h0[0][0][0])[i] = 0.f;
        (&S.h1[0][0][0])[i] = 0.f;
        (&S.c0[0][0])[i] = 0.f;
        (&S.c1[0][0])[i] = 0.f;
    }
    if (t < RPC) {
        int p = prevs[rowBase + t];
        S.prev[t]  = p & (VOCAB - 1);
        S.isend[t] = (p == EOSTOK) ? 1 : 0;
        S.len[t]   = 0;
        out[(size_t)(rowBase + t) * SEQW] = (float)p;
    }
    if (t < MAXLEN) {
        // jax.random.split, threefry_partitionable=True (foldlike):
        // keys[i] = threefry2x32(key(0,42), (hi=0, lo=i))
        S.keys[t] = tf2x32(make_uint2(0u, 42u), make_uint2(0u, (uint32_t)t));
    }
    __syncthreads();

    for (int s = 0; s < MAXLEN; s++) {
        const int cur = s & 1, nxt = cur ^ 1;

        // ---- gather x = emb[prev] into xs[r][k] ----
        {
            int k = t >> 3, r = t & 7;
            S.xs[r][k] = emb[S.prev[r] * EMB + k];
        }
        __syncthreads();

        // ---- layer 0: gates = h0 @ Whh0^T + x @ Wih0^T + b ----
        #pragma unroll 1
        for (int pass = 0; pass < NPASS; pass++) {
            int col = pass * 64 + w * 4 + c;
            float acc[4][RPC];
            #pragma unroll
            for (int g = 0; g < 4; g++)
                #pragma unroll
                for (int r = 0; r < RPC; r++) acc[g][r] = 0.f;
            kslice(acc, Whh0, &S.h0[cur][0][0], HS, col, HID, kl);
            kslice(acc, Wih0, &S.xs[0][0],      XS, col, EMB, kl);
            reduce_cell(acc, bih0, bhh0, &S.c0[0][0], &S.h0[nxt][0][0], col, kl);
        }
        __syncthreads();

        // ---- layer 1: gates = h0_new @ Wih1^T + h1 @ Whh1^T + b ----
        #pragma unroll 1
        for (int pass = 0; pass < NPASS; pass++) {
            int col = pass * 64 + w * 4 + c;
            float acc[4][RPC];
            #pragma unroll
            for (int g = 0; g < 4; g++)
                #pragma unroll
                for (int r = 0; r < RPC; r++) acc[g][r] = 0.f;
            kslice(acc, Wih1, &S.h0[nxt][0][0], HS, col, HID, kl);
            kslice(acc, Whh1, &S.h1[cur][0][0], HS, col, HID, kl);
            reduce_cell(acc, bih1, bhh1, &S.c1[0][0], &S.h1[nxt][0][0], col, kl);
        }
        __syncthreads();

        // ---- logits: part[r][v] = sum_k h1T[r][k] * Wout[v][k] ----
        {
            int v = t >> 4;            // 0..31
            int kb = t & 15;           // k-lane within group of 16
            const float* wv = Wout + (size_t)v * HID;
            const float* h1n = &S.h1[nxt][0][0];
            float p[RPC];
            #pragma unroll
            for (int r = 0; r < RPC; r++) p[r] = 0.f;
            for (int k = kb; k < HID; k += 16) {
                float wgt = __ldg(wv + k);
                #pragma unroll
                for (int r = 0; r < RPC; r++)
                    p[r] = fmaf(h1n[r * HS + k], wgt, p[r]);
            }
            #pragma unroll
            for (int off = 8; off >= 1; off >>= 1)
                #pragma unroll
                for (int r = 0; r < RPC; r++)
                    p[r] += __shfl_down_sync(0xffffffffu, p[r], off, 16);
            if (kb == 0)
                #pragma unroll
                for (int r = 0; r < RPC; r++) S.part[r][v] = p[r];
        }
        __syncthreads();

        // ---- jax.random.categorical + state update (warp r -> row r) ----
        if (t < RPC * 32) {
            int r = t >> 5, v = t & 31;
            int gr = rowBase + r;
            float logit = S.part[r][v] + bout[v];

            // random_bits (partitionable foldlike): counts (0, idx); out0^out1
            uint2 key = S.keys[s];
            uint32_t idx = (uint32_t)(gr * VOCAB + v);
            uint2 o = tf2x32(key, make_uint2(0u, idx));
            uint32_t bits = o.x ^ o.y;

            const float tiny = 1.17549435e-38f;
            float f = __uint_as_float((bits >> 9) | 0x3f800000u) - 1.0f;
            float u = fmaxf(f * (1.0f - tiny) + tiny, tiny);
            float gmb = -logf(-logf(u));
            float val = gmb + logit;

            int bi = v;   // first-index argmax (jnp.argmax semantics)
            #pragma unroll
            for (int off = 16; off > 0; off >>= 1) {
                float ov = __shfl_down_sync(0xffffffffu, val, off);
                int   oi = __shfl_down_sync(0xffffffffu, bi, off);
                if (ov > val || (ov == val && oi < bi)) { val = ov; bi = oi; }
            }
            if (v == 0) {
                int old_end = S.isend[r];
                int tok = old_end ? PADTOK : bi;
                if (!old_end) S.len[r] += 1;
                S.isend[r] = old_end | (tok == EOSTOK);
                S.prev[r] = tok;
                out[(size_t)gr * SEQW + s + 1] = (float)tok;
            }
        }
        __syncthreads();
    }

    if (write_len && t < RPC)
        out[(size_t)BATCH * SEQW + rowBase + t] = (float)(S.len[t] + 1);
}

// ---------------- launcher: resolve input roles by size signature -----------
extern "C" void kernel_launch(void* const* d_in, const int* in_sizes, int n_in,
                              void* d_out, int out_size) {
    int iprevs, iemb, iWih0, iWhh0, ibih0, ibhh0, iWih1, iWhh1, ibih1, ibhh1, iWout, ibout;
    if (n_in >= 12 && in_sizes[0] == 2048 && in_sizes[1] == 2048) {
        iprevs=0; iemb=1; iWih0=2; iWhh0=3; ibih0=4; ibhh0=5;
        iWih1=6; iWhh1=7; ibih1=8; ibhh1=9; iWout=10; ibout=11;
    } else if (n_in >= 13 && in_sizes[0] == 4194304) {
        iWhh0=0; iWhh1=1; iWih0=2; iWih1=3; iWout=4; ibhh0=5; ibhh1=6;
        ibih0=7; ibih1=8; ibout=9; iemb=10; iprevs=12;
        if (in_sizes[11] == 2048 && in_sizes[12] != 2048) iprevs = 11;
    } else if (n_in >= 13 && in_sizes[0] == 4096) {
        ibhh0=0; ibhh1=1; ibih0=2; ibih1=3; ibout=4; iemb=5; iprevs=7;
        iWhh0=8; iWhh1=9; iWih0=10; iWih1=11; iWout=12;
        if (in_sizes[6] == 2048 && in_sizes[7] != 2048) {
            iprevs=6; iWhh0=7; iWhh1=8; iWih0=9; iWih1=10; iWout=11;
        }
    } else {
        iprevs=0; iemb=1; iWih0=2; iWhh0=3; ibih0=4; ibhh0=5;
        iWih1=6; iWhh1=7; ibih1=8; ibhh1=9; iWout=10; ibout=11;
    }

    const int*   prevs = (const int*)d_in[iprevs];
    const float* emb   = (const float*)d_in[iemb];
    const float* Wih0  = (const float*)d_in[iWih0];
    const float* Whh0  = (const float*)d_in[iWhh0];
    const float* bih0  = (const float*)d_in[ibih0];
    const float* bhh0  = (const float*)d_in[ibhh0];
    const float* Wih1  = (const float*)d_in[iWih1];
    const float* Whh1  = (const float*)d_in[iWhh1];
    const float* bih1  = (const float*)d_in[ibih1];
    const float* bhh1  = (const float*)d_in[ibhh1];
    const float* Wout  = (const float*)d_in[iWout];
    const float* bout  = (const float*)d_in[ibout];
    float* out = (float*)d_out;   // __output__ dtype: float32 (R14-verified)

    cudaFuncSetAttribute(organ_persistent,
                         cudaFuncAttributeMaxDynamicSharedMemorySize,
                         (int)sizeof(Smem));
    int write_len = (out_size >= BATCH * SEQW + BATCH) ? 1 : 0;
    organ_persistent<<<NCTA, TPB, sizeof(Smem)>>>(
        prevs, emb, Wih0, Whh0, bih0, bhh0, Wih1, Whh1, bih1, bhh1,
        Wout, bout, out, write_len);
}

// round 16
// speedup vs baseline: 4.2084x; 1.0173x over previous
#include <cuda_runtime.h>
#include <cstdint>
#include <math.h>

// Problem constants (fixed: VOCAB=32, EMB=64, HID=1024, BATCH=2048, MAXLEN=100)
#define BATCH  2048
#define HID    1024
#define EMB    64
#define VOCAB  32
#define MAXLEN 100
#define SEQW   (MAXLEN+1)
#define PADTOK 0
#define EOSTOK 2

#define NCTA   256     // CTAs; each owns RPC rows for the whole generation
#define RPC    8       // rows per CTA
#define TPB    512     // threads; warp = 4 col-pairs x 8 k-lanes
#define NPASS  8       // column passes: 8 * 128 cols = 1024
#define HS     1028    // padded k-stride for h/c tiles (bank-conflict-free)
#define XS     68      // padded k-stride for x tile

// R15 ncu: L1 66% (ceiling), fma 43.8%, L2 33.6%. L1 split per 256 FMA:
// LDG 32 wf, LDS 64 wf -> activations dominate. This round: 2 cols/thread
// so each activation float4 feeds 8 gate-cols -> LDS/FMA halved.

struct Smem {
    float h0[2][RPC][HS];     // 65.8KB  layer-0 h, [buf][row][k]
    float h1[2][RPC][HS];     // 65.8KB
    float c0[RPC][HS];        // 32.9KB
    float c1[RPC][HS];        // 32.9KB
    float xs[RPC][XS];        // 2.2KB   emb[prev] gather, [row][k]
    float part[RPC][VOCAB];   // 1KB
    uint2 keys[MAXLEN];       // 800B
    int   prev[RPC];
    int   isend[RPC];
    int   len[RPC];
};                            // ~201.5KB dynamic shared

// ---------------- Threefry-2x32 (matches jax._src.prng) ----------------
__device__ __forceinline__ uint2 tf2x32(uint2 k, uint2 x) {
    uint32_t ks0 = k.x, ks1 = k.y, ks2 = k.x ^ k.y ^ 0x1BD11BDAu;
    uint32_t x0 = x.x + ks0, x1 = x.y + ks1;
#define TFR(r) { x0 += x1; x1 = __funnelshift_l(x1, x1, (r)); x1 ^= x0; }
    TFR(13) TFR(15) TFR(26) TFR(6)   x0 += ks1; x1 += ks2 + 1u;
    TFR(17) TFR(29) TFR(16) TFR(24)  x0 += ks2; x1 += ks0 + 2u;
    TFR(13) TFR(15) TFR(26) TFR(6)   x0 += ks0; x1 += ks1 + 3u;
    TFR(17) TFR(29) TFR(16) TFR(24)  x0 += ks1; x1 += ks2 + 4u;
    TFR(13) TFR(15) TFR(26) TFR(6)   x0 += ks2; x1 += ks0 + 5u;
#undef TFR
    return make_uint2(x0, x1);
}

// XLA expands logistic(x) as 0.5 + 0.5*tanh(0.5*x)
__device__ __forceinline__ float sigmoid_x(float x) { return 0.5f * tanhf(0.5f * x) + 0.5f; }

// Partial GEMM over this lane's k-slice for TWO adjacent columns.
// acc[cc][g][r] += sum_k AsT[r][k] * W[g*HID+col+cc][k]
// W loads: 8 kl-lanes cover one contiguous 128B line per (cc,g) -> coalesced.
// As loads: one float4 per row per i-iter, reused by both cols x 4 gates.
__device__ __forceinline__ void kslice2(float (&acc)[2][4][RPC],
                                        const float* __restrict__ W,
                                        const float* __restrict__ AsT, int stride,
                                        int col, int K, int kl) {
    const float* wp[2][4];
    #pragma unroll
    for (int cc = 0; cc < 2; cc++)
        #pragma unroll
        for (int g = 0; g < 4; g++)
            wp[cc][g] = W + (size_t)(g * HID + col + cc) * K + kl * 4;
    const int ni = K >> 5;
    for (int i = 0; i < ni; i++) {
        int koff = i << 5;
        float4 wv[2][4];
        #pragma unroll
        for (int cc = 0; cc < 2; cc++)
            #pragma unroll
            for (int g = 0; g < 4; g++)
                wv[cc][g] = __ldg((const float4*)(wp[cc][g] + koff));
        int kbase = koff + (kl << 2);
        #pragma unroll
        for (int r = 0; r < RPC; r++) {
            float4 a = *(const float4*)(AsT + r * stride + kbase);
            #pragma unroll
            for (int cc = 0; cc < 2; cc++)
                #pragma unroll
                for (int g = 0; g < 4; g++) {
                    acc[cc][g][r] = fmaf(wv[cc][g].x, a.x, acc[cc][g][r]);
                    acc[cc][g][r] = fmaf(wv[cc][g].y, a.y, acc[cc][g][r]);
                    acc[cc][g][r] = fmaf(wv[cc][g].z, a.z, acc[cc][g][r]);
                    acc[cc][g][r] = fmaf(wv[cc][g].w, a.w, acc[cc][g][r]);
                }
        }
    }
}

// Reduce over the 8 k-lanes, add biases, apply LSTM cell for row kl on both
// columns, store h,c.
__device__ __forceinline__ void reduce_cell2(float (&acc)[2][4][RPC],
                                             const float* __restrict__ bih,
                                             const float* __restrict__ bhh,
                                             float* __restrict__ crow,   // &c[0][0]
                                             float* __restrict__ hrow,   // &h_new[0][0]
                                             int col, int kl) {
    #pragma unroll
    for (int cc = 0; cc < 2; cc++)
        #pragma unroll
        for (int g = 0; g < 4; g++)
            #pragma unroll
            for (int r = 0; r < RPC; r++) {
                acc[cc][g][r] += __shfl_xor_sync(0xffffffffu, acc[cc][g][r], 1);
                acc[cc][g][r] += __shfl_xor_sync(0xffffffffu, acc[cc][g][r], 2);
                acc[cc][g][r] += __shfl_xor_sync(0xffffffffu, acc[cc][g][r], 4);
            }
    #pragma unroll
    for (int cc = 0; cc < 2; cc++) {
        float gi = 0.f, gf = 0.f, gg = 0.f, go = 0.f;
        #pragma unroll
        for (int r = 0; r < RPC; r++)
            if (kl == r) { gi = acc[cc][0][r]; gf = acc[cc][1][r];
                           gg = acc[cc][2][r]; go = acc[cc][3][r]; }
        int cl = col + cc;
        gi += bih[cl]         + bhh[cl];
        gf += bih[HID + cl]   + bhh[HID + cl];
        gg += bih[2*HID + cl] + bhh[2*HID + cl];
        go += bih[3*HID + cl] + bhh[3*HID + cl];
        float cold = crow[kl * HS + cl];
        float cn = sigmoid_x(gf) * cold + sigmoid_x(gi) * tanhf(gg);
        crow[kl * HS + cl] = cn;
        hrow[kl * HS + cl] = sigmoid_x(go) * tanhf(cn);
    }
}

__global__ __launch_bounds__(TPB, 1)
void organ_persistent(const int* __restrict__ prevs, const float* __restrict__ emb,
                      const float* __restrict__ Wih0, const float* __restrict__ Whh0,
                      const float* __restrict__ bih0, const float* __restrict__ bhh0,
                      const float* __restrict__ Wih1, const float* __restrict__ Whh1,
                      const float* __restrict__ bih1, const float* __restrict__ bhh1,
                      const float* __restrict__ Wout, const float* __restrict__ bout,
                      float* __restrict__ out, int write_len) {
    extern __shared__ char smem_raw[];
    Smem& S = *reinterpret_cast<Smem*>(smem_raw);
    const int t = threadIdx.x;
    const int w = t >> 5;
    const int c = (t >> 3) & 3;
    const int kl = t & 7;
    const int rowBase = blockIdx.x * RPC;

    // ---- init shared state ----
    for (int i = t; i < RPC * HS; i += TPB) {
        (&S.h0[0][0][0])[i] = 0.f;
        (&S.h1[0][0][0])[i] = 0.f;
        (&S.c0[0][0])[i] = 0.f;
        (&S.c1[0][0])[i] = 0.f;
    }
    if (t < RPC) {
        int p = prevs[rowBase + t];
        S.prev[t]  = p & (VOCAB - 1);
        S.isend[t] = (p == EOSTOK) ? 1 : 0;
        S.len[t]   = 0;
        out[(size_t)(rowBase + t) * SEQW] = (float)p;
    }
    if (t < MAXLEN) {
        // jax.random.split, threefry_partitionable=True (foldlike):
        // keys[i] = threefry2x32(key(0,42), (hi=0, lo=i))
        S.keys[t] = tf2x32(make_uint2(0u, 42u), make_uint2(0u, (uint32_t)t));
    }
    __syncthreads();

    for (int s = 0; s < MAXLEN; s++) {
        const int cur = s & 1, nxt = cur ^ 1;

        // ---- gather x = emb[prev] into xs[r][k] ----
        {
            int k = t >> 3, r = t & 7;
            S.xs[r][k] = emb[S.prev[r] * EMB + k];
        }
        __syncthreads();

        // ---- layer 0: gates = h0 @ Whh0^T + x @ Wih0^T + b ----
        #pragma unroll 1
        for (int pass = 0; pass < NPASS; pass++) {
            int col = pass * 128 + w * 8 + c * 2;
            float acc[2][4][RPC];
            #pragma unroll
            for (int cc = 0; cc < 2; cc++)
                #pragma unroll
                for (int g = 0; g < 4; g++)
                    #pragma unroll
                    for (int r = 0; r < RPC; r++) acc[cc][g][r] = 0.f;
            kslice2(acc, Whh0, &S.h0[cur][0][0], HS, col, HID, kl);
            kslice2(acc, Wih0, &S.xs[0][0],      XS, col, EMB, kl);
            reduce_cell2(acc, bih0, bhh0, &S.c0[0][0], &S.h0[nxt][0][0], col, kl);
        }
        __syncthreads();

        // ---- layer 1: gates = h0_new @ Wih1^T + h1 @ Whh1^T + b ----
        #pragma unroll 1
        for (int pass = 0; pass < NPASS; pass++) {
            int col = pass * 128 + w * 8 + c * 2;
            float acc[2][4][RPC];
            #pragma unroll
            for (int cc = 0; cc < 2; cc++)
                #pragma unroll
                for (int g = 0; g < 4; g++)
                    #pragma unroll
                    for (int r = 0; r < RPC; r++) acc[cc][g][r] = 0.f;
            kslice2(acc, Wih1, &S.h0[nxt][0][0], HS, col, HID, kl);
            kslice2(acc, Whh1, &S.h1[cur][0][0], HS, col, HID, kl);
            reduce_cell2(acc, bih1, bhh1, &S.c1[0][0], &S.h1[nxt][0][0], col, kl);
        }
        __syncthreads();

        // ---- logits: part[r][v] = sum_k h1T[r][k] * Wout[v][k] ----
        {
            int v = t >> 4;            // 0..31
            int kb = t & 15;           // k-lane within group of 16
            const float* wv = Wout + (size_t)v * HID;
            const float* h1n = &S.h1[nxt][0][0];
            float p[RPC];
            #pragma unroll
            for (int r = 0; r < RPC; r++) p[r] = 0.f;
            for (int k = kb; k < HID; k += 16) {
                float wgt = __ldg(wv + k);
                #pragma unroll
                for (int r = 0; r < RPC; r++)
                    p[r] = fmaf(h1n[r * HS + k], wgt, p[r]);
            }
            #pragma unroll
            for (int off = 8; off >= 1; off >>= 1)
                #pragma unroll
                for (int r = 0; r < RPC; r++)
                    p[r] += __shfl_down_sync(0xffffffffu, p[r], off, 16);
            if (kb == 0)
                #pragma unroll
                for (int r = 0; r < RPC; r++) S.part[r][v] = p[r];
        }
        __syncthreads();

        // ---- jax.random.categorical + state update (warp r -> row r) ----
        if (t < RPC * 32) {
            int r = t >> 5, v = t & 31;
            int gr = rowBase + r;
            float logit = S.part[r][v] + bout[v];

            // random_bits (partitionable foldlike): counts (0, idx); out0^out1
            uint2 key = S.keys[s];
            uint32_t idx = (uint32_t)(gr * VOCAB + v);
            uint2 o = tf2x32(key, make_uint2(0u, idx));
            uint32_t bits = o.x ^ o.y;

            const float tiny = 1.17549435e-38f;
            float f = __uint_as_float((bits >> 9) | 0x3f800000u) - 1.0f;
            float u = fmaxf(f * (1.0f - tiny) + tiny, tiny);
            float gmb = -logf(-logf(u));
            float val = gmb + logit;

            int bi = v;   // first-index argmax (jnp.argmax semantics)
            #pragma unroll
            for (int off = 16; off > 0; off >>= 1) {
                float ov = __shfl_down_sync(0xffffffffu, val, off);
                int   oi = __shfl_down_sync(0xffffffffu, bi, off);
                if (ov > val || (ov == val && oi < bi)) { val = ov; bi = oi; }
            }
            if (v == 0) {
                int old_end = S.isend[r];
                int tok = old_end ? PADTOK : bi;
                if (!old_end) S.len[r] += 1;
                S.isend[r] = old_end | (tok == EOSTOK);
                S.prev[r] = tok;
                out[(size_t)gr * SEQW + s + 1] = (float)tok;
            }
        }
        __syncthreads();
    }

    if (write_len && t < RPC)
        out[(size_t)BATCH * SEQW + rowBase + t] = (float)(S.len[t] + 1);
}

// ---------------- launcher: resolve input roles by size signature -----------
extern "C" void kernel_launch(void* const* d_in, const int* in_sizes, int n_in,
                              void* d_out, int out_size) {
    int iprevs, iemb, iWih0, iWhh0, ibih0, ibhh0, iWih1, iWhh1, ibih1, ibhh1, iWout, ibout;
    if (n_in >= 12 && in_sizes[0] == 2048 && in_sizes[1] == 2048) {
        iprevs=0; iemb=1; iWih0=2; iWhh0=3; ibih0=4; ibhh0=5;
        iWih1=6; iWhh1=7; ibih1=8; ibhh1=9; iWout=10; ibout=11;
    } else if (n_in >= 13 && in_sizes[0] == 4194304) {
        iWhh0=0; iWhh1=1; iWih0=2; iWih1=3; iWout=4; ibhh0=5; ibhh1=6;
        ibih0=7; ibih1=8; ibout=9; iemb=10; iprevs=12;
        if (in_sizes[11] == 2048 && in_sizes[12] != 2048) iprevs = 11;
    } else if (n_in >= 13 && in_sizes[0] == 4096) {
        ibhh0=0; ibhh1=1; ibih0=2; ibih1=3; ibout=4; iemb=5; iprevs=7;
        iWhh0=8; iWhh1=9; iWih0=10; iWih1=11; iWout=12;
        if (in_sizes[6] == 2048 && in_sizes[7] != 2048) {
            iprevs=6; iWhh0=7; iWhh1=8; iWih0=9; iWih1=10; iWout=11;
        }
    } else {
        iprevs=0; iemb=1; iWih0=2; iWhh0=3; ibih0=4; ibhh0=5;
        iWih1=6; iWhh1=7; ibih1=8; ibhh1=9; iWout=10; ibout=11;
    }

    const int*   prevs = (const int*)d_in[iprevs];
    const float* emb   = (const float*)d_in[iemb];
    const float* Wih0  = (const float*)d_in[iWih0];
    const float* Whh0  = (const float*)d_in[iWhh0];
    const float* bih0  = (const float*)d_in[ibih0];
    const float* bhh0  = (const float*)d_in[ibhh0];
    const float* Wih1  = (const float*)d_in[iWih1];
    const float* Whh1  = (const float*)d_in[iWhh1];
    const float* bih1  = (const float*)d_in[ibih1];
    const float* bhh1  = (const float*)d_in[ibhh1];
    const float* Wout  = (const float*)d_in[iWout];
    const float* bout  = (const float*)d_in[ibout];
    float* out = (float*)d_out;   // __output__ dtype: float32 (R14-verified)

    cudaFuncSetAttribute(organ_persistent,
                         cudaFuncAttributeMaxDynamicSharedMemorySize,
                         (int)sizeof(Smem));
    int write_len = (out_size >= BATCH * SEQW + BATCH) ? 1 : 0;
    organ_persistent<<<NCTA, TPB, sizeof(Smem)>>>(
        prevs, emb, Wih0, Whh0, bih0, bhh0, Wih1, Whh1, bih1, bhh1,
        Wout, bout, out, write_len);
}